// round 16
// baseline (speedup 1.0000x reference)
#include <cuda_runtime.h>
#include <float.h>
#include <math.h>

#define FULLMASK 0xffffffffu

typedef unsigned long long ull;

static const int NN = 20000;   // nodes
static const int NE = 640000;  // edges
static const int NG = 64;      // graphs

// ---------------- packed f32x2 helpers (Blackwell FFMA2 path) ----------------
__device__ __forceinline__ ull pack2(float x, float y) {
    ull r; asm("mov.b64 %0,{%1,%2};" : "=l"(r) : "f"(x), "f"(y)); return r;
}
__device__ __forceinline__ ull dup2(float x) { return pack2(x, x); }
__device__ __forceinline__ void unpack2(ull v, float& x, float& y) {
    asm("mov.b64 {%0,%1},%2;" : "=f"(x), "=f"(y) : "l"(v));
}
__device__ __forceinline__ void fma2(ull& d, ull a, ull b) {
    asm("fma.rn.f32x2 %0,%1,%2,%0;" : "+l"(d) : "l"(a), "l"(b));
}
__device__ __forceinline__ ull add2(ull a, ull b) {
    ull r; asm("add.rn.f32x2 %0,%1,%2;" : "=l"(r) : "l"(a), "l"(b)); return r;
}
__device__ __forceinline__ ull mul2(ull a, ull b) {
    ull r; asm("mul.rn.f32x2 %0,%1,%2;" : "=l"(r) : "l"(a), "l"(b)); return r;
}
// L1-streamed 16B load, opaque to NVVM hoisting (keeps We out of registers)
__device__ __forceinline__ void ldg_v2u64(ull& a, ull& b, const void* p) {
    asm volatile("ld.global.nc.v2.u64 {%0,%1},[%2];" : "=l"(a), "=l"(b) : "l"(p));
}

// ---------------- scratch ----------------------------------------------------
__device__ float g_XL[20000 * 512];
__device__ float g_XR[20000 * 512];
__device__ float g_HA[20000 * 256];
__device__ float g_HB[20000 * 256];
__device__ int   g_cnt[20000];
__device__ int   g_rowptr[20001];
__device__ int   g_cursor[20000];
__device__ int   g_csrc[640000];
__device__ int   g_ceid[640000];
__device__ __align__(16) float g_eacsr[640000 * 16];
__device__ int   g_gcnt[64];

// ---------------- CSR build --------------------------------------------------
__global__ void k_zero_cnt(int* cnt, int n) {
    int i = blockIdx.x * blockDim.x + threadIdx.x;
    if (i < n) cnt[i] = 0;
}

__global__ void k_hist(const int* __restrict__ ei, int* cnt, int E) {
    int e = blockIdx.x * blockDim.x + threadIdx.x;
    if (e < E) atomicAdd(&cnt[ei[E + e]], 1);
}

__global__ void k_scan(const int* __restrict__ cnt, int* rowptr, int* cursor, int n) {
    __shared__ int wsum[32];
    __shared__ int carry_s;
    int tid = threadIdx.x, lane = tid & 31, wid = tid >> 5;
    if (tid == 0) { carry_s = 0; rowptr[0] = 0; }
    __syncthreads();
    for (int base = 0; base < n; base += 1024) {
        int i = base + tid;
        int v = (i < n) ? cnt[i] : 0;
        int x = v;
#pragma unroll
        for (int off = 1; off < 32; off <<= 1) {
            int t = __shfl_up_sync(FULLMASK, x, off);
            if (lane >= off) x += t;
        }
        if (lane == 31) wsum[wid] = x;
        __syncthreads();
        if (wid == 0) {
            int w = wsum[lane];
#pragma unroll
            for (int off = 1; off < 32; off <<= 1) {
                int t = __shfl_up_sync(FULLMASK, w, off);
                if (lane >= off) w += t;
            }
            wsum[lane] = w;
        }
        __syncthreads();
        int incl = x + (wid > 0 ? wsum[wid - 1] : 0) + carry_s;
        if (i < n) { rowptr[i + 1] = incl; cursor[i] = incl - v; }
        __syncthreads();
        if (tid == 1023) carry_s = incl;
        __syncthreads();
    }
}

__global__ void k_scatter(const int* __restrict__ ei, int* cursor,
                          int* __restrict__ csrc, int* __restrict__ ceid, int E) {
    int e = blockIdx.x * blockDim.x + threadIdx.x;
    if (e < E) {
        int dst = ei[E + e];
        int p = atomicAdd(&cursor[dst], 1);
        csrc[p] = ei[e];
        ceid[p] = e;
    }
}

__global__ void k_gather_ea(const float* __restrict__ EA, const int* __restrict__ ceid,
                            float* __restrict__ eacsr, int E) {
    int p = blockIdx.x * blockDim.x + threadIdx.x;
    if (p < E) {
        int e = ceid[p];
        const float4* s = (const float4*)(EA + (long)e * 16);
        float4* d = (float4*)(eacsr + (long)p * 16);
        d[0] = s[0]; d[1] = s[1]; d[2] = s[2]; d[3] = s[3];
    }
}

// ---------------- fp32 GEMM (FFMA2): C[M,N] = A[M,K]@B[K,N] + bias -----------
// R7 single-stage version (measured best: 44.9us L0, fma=42%).
__global__ __launch_bounds__(256, 3)
void k_gemm_bias(const float* __restrict__ A, const float* __restrict__ B,
                 const float* __restrict__ bias, float* __restrict__ C,
                 int M, int N, int K)
{
    __shared__ __align__(16) float As[8][132];
    __shared__ __align__(16) float Bs[8][64];
    const int t = threadIdx.x;
    const int m0 = blockIdx.y * 128;
    const int n0 = blockIdx.x * 64;
    const int tx = t & 15, ty = t >> 4;
    const int ar = t >> 1, ak = (t & 1) * 4;
    const int bk = t >> 4, bn = (t & 15) * 4;

    ull c2[8][2];
#pragma unroll
    for (int i = 0; i < 8; i++) { c2[i][0] = 0ULL; c2[i][1] = 0ULL; }

    float4 av = make_float4(0.f, 0.f, 0.f, 0.f);
    if (m0 + ar < M) av = *(const float4*)(A + (long)(m0 + ar) * K + ak);
    float4 bv = make_float4(0.f, 0.f, 0.f, 0.f);
    if (t < 128) bv = *(const float4*)(B + (long)bk * N + n0 + bn);

    int k0 = 0;
    for (;;) {
        As[ak + 0][ar] = av.x;
        As[ak + 1][ar] = av.y;
        As[ak + 2][ar] = av.z;
        As[ak + 3][ar] = av.w;
        if (t < 128) *(float4*)&Bs[bk][bn] = bv;
        __syncthreads();

        k0 += 8;
        bool more = (k0 < K);
        if (more) {
            av = make_float4(0.f, 0.f, 0.f, 0.f);
            if (m0 + ar < M) av = *(const float4*)(A + (long)(m0 + ar) * K + k0 + ak);
            if (t < 128) bv = *(const float4*)(B + (long)(k0 + bk) * N + n0 + bn);
        }

#pragma unroll
        for (int kk = 0; kk < 8; kk++) {
            float4 a0 = *(const float4*)&As[kk][ty * 8];
            float4 a1 = *(const float4*)&As[kk][ty * 8 + 4];
            ulonglong2 bb = *(const ulonglong2*)&Bs[kk][tx * 4];
            ull ad[8];
            ad[0] = dup2(a0.x); ad[1] = dup2(a0.y); ad[2] = dup2(a0.z); ad[3] = dup2(a0.w);
            ad[4] = dup2(a1.x); ad[5] = dup2(a1.y); ad[6] = dup2(a1.z); ad[7] = dup2(a1.w);
#pragma unroll
            for (int i = 0; i < 8; i++) {
                fma2(c2[i][0], ad[i], bb.x);
                fma2(c2[i][1], ad[i], bb.y);
            }
        }
        if (!more) break;
        __syncthreads();
    }

    float4 bb = *(const float4*)(bias + n0 + tx * 4);
#pragma unroll
    for (int i = 0; i < 8; i++) {
        int row = m0 + ty * 8 + i;
        if (row < M) {
            float4 o;
            unpack2(c2[i][0], o.x, o.y);
            unpack2(c2[i][1], o.z, o.w);
            o.x += bb.x; o.y += bb.y; o.z += bb.z; o.w += bb.w;
            *(float4*)(C + (long)row * N + n0 + tx * 4) = o;
        }
    }
}

// ---------------- GATv2 attention: warp-granular + streamed We ---------------
// 8 ch/lane; warp covers 256 ch; WPN = HC/256 warps per node.
// We slice is NOT register-resident: each edge re-reads its 16x(4 f32x2) slice
// via ld.global.nc (L1-hot, 16-32KB table) -> regs drop ~254 -> ~128 ->
// 16 warps/SM at 32-thread blocks. launch_bounds(64,8) caps ptxas at 128 regs.
template<int HC, int C, bool CONCAT>
__global__ __launch_bounds__(64, 8)
void k_gat(const float* __restrict__ XL, const float* __restrict__ XR,
           const float* __restrict__ EACSR, const float* __restrict__ att,
           const float* __restrict__ bias, const float* __restrict__ We,
           const int* __restrict__ rowptr, const int* __restrict__ csrc,
           float* __restrict__ Hout, int N)
{
    constexpr int WPN = HC / 256;
    constexpr int LPH = C / 8;
    __shared__ float s_red[128];    // layer-2 head-mean exchange (1 node/block)

    int widx = threadIdx.x >> 5;
    int lane = threadIdx.x & 31;
    int gw = blockIdx.x * ((int)blockDim.x >> 5) + widx;
    int n = gw / WPN;
    int half = gw - n * WPN;
    int cbase = half * 256 + lane * 8;

    const char* wbase = (const char*)(We + cbase);   // + k*HC*4 per k-row

    float att_r[8];
    {
        float4 a = *(const float4*)(att + cbase);
        float4 b = *(const float4*)(att + cbase + 4);
        att_r[0] = a.x; att_r[1] = a.y; att_r[2] = a.z; att_r[3] = a.w;
        att_r[4] = b.x; att_r[5] = b.y; att_r[6] = b.z; att_r[7] = b.w;
    }
    ull xr2[4];
    {
        const ulonglong2* q = (const ulonglong2*)(XR + (long)n * HC + cbase);
        ulonglong2 u0 = q[0], u1 = q[1];
        xr2[0] = u0.x; xr2[1] = u0.y; xr2[2] = u1.x; xr2[3] = u1.y;
    }

    int e0 = rowptr[n], e1 = rowptr[n + 1];
    float m = -3.0e38f, s = 0.f;
    ull acc2[4] = {0ULL, 0ULL, 0ULL, 0ULL};

    float4 cA, cB, cC, cD;
    if (e0 < e1) {
        const float4* q = (const float4*)(EACSR + (long)e0 * 16);
        cA = q[0]; cB = q[1]; cC = q[2]; cD = q[3];
    }

    for (int pb = e0; pb < e1; pb += 32) {
        int myp = pb + lane;
        int msrc = __ldg(&csrc[(myp < e1) ? myp : e1 - 1]);
        int cnt = min(32, e1 - pb);

        ulonglong2 cx0, cx1;
        {
            int s0 = __shfl_sync(FULLMASK, msrc, 0);
            const ulonglong2* xq = (const ulonglong2*)(XL + (long)s0 * HC + cbase);
            cx0 = xq[0]; cx1 = xq[1];
        }
        for (int i = 0; i < cnt; i++) {
            float4 uA = cA, uB = cB, uC = cC, uD = cD;
            ulonglong2 ux0 = cx0, ux1 = cx1;
            if (pb + i + 1 < e1) {
                const float4* q = (const float4*)(EACSR + (long)(pb + i + 1) * 16);
                cA = q[0]; cB = q[1]; cC = q[2]; cD = q[3];
            }
            if (i + 1 < cnt) {
                int sn = __shfl_sync(FULLMASK, msrc, i + 1);
                const ulonglong2* xq = (const ulonglong2*)(XL + (long)sn * HC + cbase);
                cx0 = xq[0]; cx1 = xq[1];
            }
            float ea[16] = {uA.x, uA.y, uA.z, uA.w, uB.x, uB.y, uB.z, uB.w,
                            uC.x, uC.y, uC.z, uC.w, uD.x, uD.y, uD.z, uD.w};
            ull xl2[4] = {ux0.x, ux0.y, ux1.x, ux1.y};

            ull v0 = add2(xl2[0], xr2[0]);
            ull v1 = add2(xl2[1], xr2[1]);
            ull v2 = add2(xl2[2], xr2[2]);
            ull v3 = add2(xl2[3], xr2[3]);
#pragma unroll
            for (int k = 0; k < 16; k++) {
                ull wa, wb, wc, wd;
                ldg_v2u64(wa, wb, wbase + (long)k * HC * 4);
                ldg_v2u64(wc, wd, wbase + (long)k * HC * 4 + 16);
                ull ak = dup2(ea[k]);
                fma2(v0, ak, wa);
                fma2(v1, ak, wb);
                fma2(v2, ak, wc);
                fma2(v3, ak, wd);
            }
            float f[8];
            unpack2(v0, f[0], f[1]); unpack2(v1, f[2], f[3]);
            unpack2(v2, f[4], f[5]); unpack2(v3, f[6], f[7]);
            float part = 0.f;
#pragma unroll
            for (int j = 0; j < 8; j++) {
                float vv = f[j];
                part = fmaf(att_r[j], fmaxf(vv, 0.2f * vv), part);
            }
#pragma unroll
            for (int off = 1; off < LPH; off <<= 1)
                part += __shfl_xor_sync(FULLMASK, part, off);

            if (part > m) {
                float sc = __expf(m - part);
                s *= sc;
                ull sc2 = dup2(sc);
#pragma unroll
                for (int j = 0; j < 4; j++) acc2[j] = mul2(acc2[j], sc2);
                m = part;
            }
            float pe = __expf(part - m);
            s += pe;
            ull pe2 = dup2(pe);
            fma2(acc2[0], pe2, xl2[0]);
            fma2(acc2[1], pe2, xl2[1]);
            fma2(acc2[2], pe2, xl2[2]);
            fma2(acc2[3], pe2, xl2[3]);
        }
    }

    float inv = (e1 > e0) ? (1.f / s) : 0.f;
    float r[8];
    unpack2(acc2[0], r[0], r[1]); unpack2(acc2[1], r[2], r[3]);
    unpack2(acc2[2], r[4], r[5]); unpack2(acc2[3], r[6], r[7]);

    if (CONCAT) {
        float4 b0 = *(const float4*)(bias + cbase);
        float4 b1 = *(const float4*)(bias + cbase + 4);
        float4 o0, o1;
        o0.x = fmaf(r[0], inv, b0.x); o0.y = fmaf(r[1], inv, b0.y);
        o0.z = fmaf(r[2], inv, b0.z); o0.w = fmaf(r[3], inv, b0.w);
        o1.x = fmaf(r[4], inv, b1.x); o1.y = fmaf(r[5], inv, b1.y);
        o1.z = fmaf(r[6], inv, b1.z); o1.w = fmaf(r[7], inv, b1.w);
        float* q = Hout + (long)n * HC + cbase;
        *(float4*)q = o0;
        *(float4*)(q + 4) = o1;
    } else {
        // mean over 4 heads: shfl 16 pairs the warp's 2 heads; the node's two
        // warps (same block) combine through shared memory.
#pragma unroll
        for (int j = 0; j < 8; j++) {
            r[j] *= inv;
            r[j] += __shfl_xor_sync(FULLMASK, r[j], 16);
        }
        int c = (lane & 15) * 8;
        if (half == 0 && lane < 16) {
#pragma unroll
            for (int j = 0; j < 8; j++) s_red[c + j] = r[j];
        }
        __syncthreads();
        if (half == 1 && lane < 16) {
            float* q = Hout + (long)n * C + c;
#pragma unroll
            for (int j = 0; j < 8; j++)
                q[j] = bias[c + j] + 0.25f * (r[j] + s_red[c + j]);
        }
    }
}

// ---------------- pooling ----------------------------------------------------
__global__ void k_pool_init(float* out, int* gcnt) {
    int i = blockIdx.x * blockDim.x + threadIdx.x;
    if (i < NG * 256) out[i] = ((i & 255) < 128) ? -FLT_MAX : 0.f;
    if (i < NG) gcnt[i] = 0;
}

__global__ void k_pool_acc(const float* __restrict__ H, const int* __restrict__ batch,
                           float* out, int* gcnt) {
    int i = blockIdx.x * blockDim.x + threadIdx.x;
    if (i >= NN * 128) return;
    int nd = i >> 7, c = i & 127;
    int g = batch[nd];
    float v = H[i];
    float* mx = out + g * 256 + c;
    if (v >= 0.f) atomicMax((int*)mx, __float_as_int(v));
    else atomicMin((unsigned int*)mx, __float_as_uint(v));
    atomicAdd(out + g * 256 + 128 + c, v);
    if (c == 0) atomicAdd(&gcnt[g], 1);
}

__global__ void k_pool_fin(float* out, const int* __restrict__ gcnt) {
    int i = blockIdx.x * blockDim.x + threadIdx.x;
    if (i < NG * 128) {
        int g = i >> 7, c = i & 127;
        float cnt = (float)(gcnt[g] > 0 ? gcnt[g] : 1);
        out[g * 256 + 128 + c] /= cnt;
    }
}

// ---------------- launch -----------------------------------------------------
extern "C" void kernel_launch(void* const* d_in, const int* in_sizes, int n_in,
                              void* d_out, int out_size)
{
    const float* x     = (const float*)d_in[0];
    const float* ea    = (const float*)d_in[1];
    const int*   ei    = (const int*)d_in[2];
    const int*   batch = (const int*)d_in[3];
    const float* Wl[3] = {(const float*)d_in[4],  (const float*)d_in[11], (const float*)d_in[18]};
    const float* bl[3] = {(const float*)d_in[5],  (const float*)d_in[12], (const float*)d_in[19]};
    const float* Wr[3] = {(const float*)d_in[6],  (const float*)d_in[13], (const float*)d_in[20]};
    const float* br[3] = {(const float*)d_in[7],  (const float*)d_in[14], (const float*)d_in[21]};
    const float* We[3] = {(const float*)d_in[8],  (const float*)d_in[15], (const float*)d_in[22]};
    const float* At[3] = {(const float*)d_in[9],  (const float*)d_in[16], (const float*)d_in[23]};
    const float* Bi[3] = {(const float*)d_in[10], (const float*)d_in[17], (const float*)d_in[24]};
    float* out = (float*)d_out;

    float *XL, *XR, *HA, *HB, *eacsr;
    int *cnt, *rowptr, *cursor, *csrc, *ceid, *gcnt;
    cudaGetSymbolAddress((void**)&XL, g_XL);
    cudaGetSymbolAddress((void**)&XR, g_XR);
    cudaGetSymbolAddress((void**)&HA, g_HA);
    cudaGetSymbolAddress((void**)&HB, g_HB);
    cudaGetSymbolAddress((void**)&cnt, g_cnt);
    cudaGetSymbolAddress((void**)&rowptr, g_rowptr);
    cudaGetSymbolAddress((void**)&cursor, g_cursor);
    cudaGetSymbolAddress((void**)&csrc, g_csrc);
    cudaGetSymbolAddress((void**)&ceid, g_ceid);
    cudaGetSymbolAddress((void**)&eacsr, g_eacsr);
    cudaGetSymbolAddress((void**)&gcnt, g_gcnt);

    const int MT = (NN + 127) / 128;  // 157

    // ---- CSR histogram + scan (launches 1-3) ----
    k_zero_cnt<<<(NN + 255) / 256, 256>>>(cnt, NN);
    k_hist<<<(NE + 255) / 256, 256>>>(ei, cnt, NE);
    k_scan<<<1, 1024>>>(cnt, rowptr, cursor, NN);

    // ---- launch 4 = ncu capture slot: first GEMM ----
    k_gemm_bias<<<dim3(4, MT), 256>>>(x, Wl[0], bl[0], XL, NN, 256, 128);
    k_gemm_bias<<<dim3(4, MT), 256>>>(x, Wr[0], br[0], XR, NN, 256, 128);

    // ---- finish CSR ----
    k_scatter<<<(NE + 255) / 256, 256>>>(ei, cursor, csrc, ceid, NE);
    k_gather_ea<<<(NE + 255) / 256, 256>>>(ea, ceid, eacsr, NE);

    // ---- layer 0 attention: one 32-thread block per node ----
    k_gat<256, 64, true><<<NN, 32>>>(XL, XR, eacsr, At[0], Bi[0], We[0],
                                     rowptr, csrc, HA, NN);

    // ---- layer 1 ----
    k_gemm_bias<<<dim3(4, MT), 256>>>(HA, Wl[1], bl[1], XL, NN, 256, 256);
    k_gemm_bias<<<dim3(4, MT), 256>>>(HA, Wr[1], br[1], XR, NN, 256, 256);
    k_gat<256, 64, true><<<NN, 32>>>(XL, XR, eacsr, At[1], Bi[1], We[1],
                                     rowptr, csrc, HB, NN);

    // ---- layer 2 (mean over heads): one 64-thread block per node ----
    k_gemm_bias<<<dim3(8, MT), 256>>>(HB, Wl[2], bl[2], XL, NN, 512, 256);
    k_gemm_bias<<<dim3(8, MT), 256>>>(HB, Wr[2], br[2], XR, NN, 512, 256);
    k_gat<512, 128, false><<<NN, 64>>>(XL, XR, eacsr, At[2], Bi[2], We[2],
                                       rowptr, csrc, HA, NN);

    // ---- pooling ----
    k_pool_init<<<64, 256>>>(out, gcnt);
    k_pool_acc<<<(NN * 128 + 255) / 256, 256>>>(HA, batch, out, gcnt);
    k_pool_fin<<<32, 256>>>(out, gcnt);
}

// round 17
// speedup vs baseline: 1.7451x; 1.7451x over previous
#include <cuda_runtime.h>
#include <float.h>
#include <math.h>

#define FULLMASK 0xffffffffu

typedef unsigned long long ull;

static const int NN = 20000;   // nodes
static const int NE = 640000;  // edges
static const int NG = 64;      // graphs

// ---------------- packed f32x2 helpers (Blackwell FFMA2 path) ----------------
__device__ __forceinline__ ull pack2(float x, float y) {
    ull r; asm("mov.b64 %0,{%1,%2};" : "=l"(r) : "f"(x), "f"(y)); return r;
}
__device__ __forceinline__ ull dup2(float x) { return pack2(x, x); }
__device__ __forceinline__ void unpack2(ull v, float& x, float& y) {
    asm("mov.b64 {%0,%1},%2;" : "=f"(x), "=f"(y) : "l"(v));
}
__device__ __forceinline__ void fma2(ull& d, ull a, ull b) {
    asm("fma.rn.f32x2 %0,%1,%2,%0;" : "+l"(d) : "l"(a), "l"(b));
}
__device__ __forceinline__ ull add2(ull a, ull b) {
    ull r; asm("add.rn.f32x2 %0,%1,%2;" : "=l"(r) : "l"(a), "l"(b)); return r;
}
__device__ __forceinline__ ull mul2(ull a, ull b) {
    ull r; asm("mul.rn.f32x2 %0,%1,%2;" : "=l"(r) : "l"(a), "l"(b)); return r;
}

// ---------------- scratch ----------------------------------------------------
__device__ float g_XL[20000 * 512];
__device__ float g_XR[20000 * 512];
__device__ float g_HA[20000 * 256];
__device__ float g_HB[20000 * 256];
__device__ int   g_cnt[20000];
__device__ int   g_rowptr[20001];
__device__ int   g_cursor[20000];
__device__ int   g_csrc[640000];
__device__ int   g_ceid[640000];
__device__ __align__(16) float g_eacsr[640000 * 16];
__device__ int   g_gcnt[64];

// ---------------- CSR build --------------------------------------------------
__global__ void k_zero_cnt(int* cnt, int n) {
    int i = blockIdx.x * blockDim.x + threadIdx.x;
    if (i < n) cnt[i] = 0;
}

__global__ void k_hist(const int* __restrict__ ei, int* cnt, int E) {
    int e = blockIdx.x * blockDim.x + threadIdx.x;
    if (e < E) atomicAdd(&cnt[ei[E + e]], 1);
}

__global__ void k_scan(const int* __restrict__ cnt, int* rowptr, int* cursor, int n) {
    __shared__ int wsum[32];
    __shared__ int carry_s;
    int tid = threadIdx.x, lane = tid & 31, wid = tid >> 5;
    if (tid == 0) { carry_s = 0; rowptr[0] = 0; }
    __syncthreads();
    for (int base = 0; base < n; base += 1024) {
        int i = base + tid;
        int v = (i < n) ? cnt[i] : 0;
        int x = v;
#pragma unroll
        for (int off = 1; off < 32; off <<= 1) {
            int t = __shfl_up_sync(FULLMASK, x, off);
            if (lane >= off) x += t;
        }
        if (lane == 31) wsum[wid] = x;
        __syncthreads();
        if (wid == 0) {
            int w = wsum[lane];
#pragma unroll
            for (int off = 1; off < 32; off <<= 1) {
                int t = __shfl_up_sync(FULLMASK, w, off);
                if (lane >= off) w += t;
            }
            wsum[lane] = w;
        }
        __syncthreads();
        int incl = x + (wid > 0 ? wsum[wid - 1] : 0) + carry_s;
        if (i < n) { rowptr[i + 1] = incl; cursor[i] = incl - v; }
        __syncthreads();
        if (tid == 1023) carry_s = incl;
        __syncthreads();
    }
}

__global__ void k_scatter(const int* __restrict__ ei, int* cursor,
                          int* __restrict__ csrc, int* __restrict__ ceid, int E) {
    int e = blockIdx.x * blockDim.x + threadIdx.x;
    if (e < E) {
        int dst = ei[E + e];
        int p = atomicAdd(&cursor[dst], 1);
        csrc[p] = ei[e];
        ceid[p] = e;
    }
}

__global__ void k_gather_ea(const float* __restrict__ EA, const int* __restrict__ ceid,
                            float* __restrict__ eacsr, int E) {
    int p = blockIdx.x * blockDim.x + threadIdx.x;
    if (p < E) {
        int e = ceid[p];
        const float4* s = (const float4*)(EA + (long)e * 16);
        float4* d = (float4*)(eacsr + (long)p * 16);
        d[0] = s[0]; d[1] = s[1]; d[2] = s[2]; d[3] = s[3];
    }
}

// ---------------- fp32 GEMM (FFMA2): C[M,N] = A[M,K]@B[K,N] + bias -----------
// R7 single-stage version (measured best: 44.9us L0, fma=42%).
__global__ __launch_bounds__(256, 3)
void k_gemm_bias(const float* __restrict__ A, const float* __restrict__ B,
                 const float* __restrict__ bias, float* __restrict__ C,
                 int M, int N, int K)
{
    __shared__ __align__(16) float As[8][132];
    __shared__ __align__(16) float Bs[8][64];
    const int t = threadIdx.x;
    const int m0 = blockIdx.y * 128;
    const int n0 = blockIdx.x * 64;
    const int tx = t & 15, ty = t >> 4;
    const int ar = t >> 1, ak = (t & 1) * 4;
    const int bk = t >> 4, bn = (t & 15) * 4;

    ull c2[8][2];
#pragma unroll
    for (int i = 0; i < 8; i++) { c2[i][0] = 0ULL; c2[i][1] = 0ULL; }

    float4 av = make_float4(0.f, 0.f, 0.f, 0.f);
    if (m0 + ar < M) av = *(const float4*)(A + (long)(m0 + ar) * K + ak);
    float4 bv = make_float4(0.f, 0.f, 0.f, 0.f);
    if (t < 128) bv = *(const float4*)(B + (long)bk * N + n0 + bn);

    int k0 = 0;
    for (;;) {
        As[ak + 0][ar] = av.x;
        As[ak + 1][ar] = av.y;
        As[ak + 2][ar] = av.z;
        As[ak + 3][ar] = av.w;
        if (t < 128) *(float4*)&Bs[bk][bn] = bv;
        __syncthreads();

        k0 += 8;
        bool more = (k0 < K);
        if (more) {
            av = make_float4(0.f, 0.f, 0.f, 0.f);
            if (m0 + ar < M) av = *(const float4*)(A + (long)(m0 + ar) * K + k0 + ak);
            if (t < 128) bv = *(const float4*)(B + (long)(k0 + bk) * N + n0 + bn);
        }

#pragma unroll
        for (int kk = 0; kk < 8; kk++) {
            float4 a0 = *(const float4*)&As[kk][ty * 8];
            float4 a1 = *(const float4*)&As[kk][ty * 8 + 4];
            ulonglong2 bb = *(const ulonglong2*)&Bs[kk][tx * 4];
            ull ad[8];
            ad[0] = dup2(a0.x); ad[1] = dup2(a0.y); ad[2] = dup2(a0.z); ad[3] = dup2(a0.w);
            ad[4] = dup2(a1.x); ad[5] = dup2(a1.y); ad[6] = dup2(a1.z); ad[7] = dup2(a1.w);
#pragma unroll
            for (int i = 0; i < 8; i++) {
                fma2(c2[i][0], ad[i], bb.x);
                fma2(c2[i][1], ad[i], bb.y);
            }
        }
        if (!more) break;
        __syncthreads();
    }

    float4 bb = *(const float4*)(bias + n0 + tx * 4);
#pragma unroll
    for (int i = 0; i < 8; i++) {
        int row = m0 + ty * 8 + i;
        if (row < M) {
            float4 o;
            unpack2(c2[i][0], o.x, o.y);
            unpack2(c2[i][1], o.z, o.w);
            o.x += bb.x; o.y += bb.y; o.z += bb.z; o.w += bb.w;
            *(float4*)(C + (long)row * N + n0 + tx * 4) = o;
        }
    }
}

// ---------------- GATv2 attention: warp-granular blocks ----------------------
// 8 ch/lane; warp covers 256 ch; WPN = HC/256 warps per node.
// Launch: CONCAT layers <<<N, 32>>> (one warp = one block = one node, so nodes
// retire independently — no intra-block max-degree gating); layer 2 <<<N, 64>>>
// (the node's 2 cooperating warps share a block for the smem head-mean).
template<int HC, int C, bool CONCAT>
__global__ __launch_bounds__(128)
void k_gat(const float* __restrict__ XL, const float* __restrict__ XR,
           const float* __restrict__ EACSR, const float* __restrict__ att,
           const float* __restrict__ bias, const float* __restrict__ We,
           const int* __restrict__ rowptr, const int* __restrict__ csrc,
           float* __restrict__ Hout, int N)
{
    constexpr int WPN = HC / 256;
    constexpr int LPH = C / 8;
    __shared__ float s_red[128];    // layer-2 head-mean exchange (1 node/block)

    int widx = threadIdx.x >> 5;
    int lane = threadIdx.x & 31;
    int gw = blockIdx.x * ((int)blockDim.x >> 5) + widx;
    int n = gw / WPN;
    int half = gw - n * WPN;
    int cbase = half * 256 + lane * 8;

    ull w2[16][4];
#pragma unroll
    for (int k = 0; k < 16; k++) {
        const ulonglong2* q = (const ulonglong2*)(We + k * HC + cbase);
        ulonglong2 u0 = q[0], u1 = q[1];
        w2[k][0] = u0.x; w2[k][1] = u0.y; w2[k][2] = u1.x; w2[k][3] = u1.y;
    }
    float att_r[8];
    {
        float4 a = *(const float4*)(att + cbase);
        float4 b = *(const float4*)(att + cbase + 4);
        att_r[0] = a.x; att_r[1] = a.y; att_r[2] = a.z; att_r[3] = a.w;
        att_r[4] = b.x; att_r[5] = b.y; att_r[6] = b.z; att_r[7] = b.w;
    }
    ull xr2[4];
    {
        const ulonglong2* q = (const ulonglong2*)(XR + (long)n * HC + cbase);
        ulonglong2 u0 = q[0], u1 = q[1];
        xr2[0] = u0.x; xr2[1] = u0.y; xr2[2] = u1.x; xr2[3] = u1.y;
    }

    int e0 = rowptr[n], e1 = rowptr[n + 1];
    float m = -3.0e38f, s = 0.f;
    ull acc2[4] = {0ULL, 0ULL, 0ULL, 0ULL};

    float4 cA, cB, cC, cD;
    if (e0 < e1) {
        const float4* q = (const float4*)(EACSR + (long)e0 * 16);
        cA = q[0]; cB = q[1]; cC = q[2]; cD = q[3];
    }

    for (int pb = e0; pb < e1; pb += 32) {
        int myp = pb + lane;
        int msrc = __ldg(&csrc[(myp < e1) ? myp : e1 - 1]);
        int cnt = min(32, e1 - pb);

        ulonglong2 cx0, cx1;
        {
            int s0 = __shfl_sync(FULLMASK, msrc, 0);
            const ulonglong2* xq = (const ulonglong2*)(XL + (long)s0 * HC + cbase);
            cx0 = xq[0]; cx1 = xq[1];
        }
        for (int i = 0; i < cnt; i++) {
            float4 uA = cA, uB = cB, uC = cC, uD = cD;
            ulonglong2 ux0 = cx0, ux1 = cx1;
            if (pb + i + 1 < e1) {
                const float4* q = (const float4*)(EACSR + (long)(pb + i + 1) * 16);
                cA = q[0]; cB = q[1]; cC = q[2]; cD = q[3];
            }
            if (i + 1 < cnt) {
                int sn = __shfl_sync(FULLMASK, msrc, i + 1);
                const ulonglong2* xq = (const ulonglong2*)(XL + (long)sn * HC + cbase);
                cx0 = xq[0]; cx1 = xq[1];
            }
            float ea[16] = {uA.x, uA.y, uA.z, uA.w, uB.x, uB.y, uB.z, uB.w,
                            uC.x, uC.y, uC.z, uC.w, uD.x, uD.y, uD.z, uD.w};
            ull xl2[4] = {ux0.x, ux0.y, ux1.x, ux1.y};

            ull v0 = add2(xl2[0], xr2[0]);
            ull v1 = add2(xl2[1], xr2[1]);
            ull v2 = add2(xl2[2], xr2[2]);
            ull v3 = add2(xl2[3], xr2[3]);
#pragma unroll
            for (int k = 0; k < 16; k++) {
                ull ak = dup2(ea[k]);
                fma2(v0, ak, w2[k][0]);
                fma2(v1, ak, w2[k][1]);
                fma2(v2, ak, w2[k][2]);
                fma2(v3, ak, w2[k][3]);
            }
            float f[8];
            unpack2(v0, f[0], f[1]); unpack2(v1, f[2], f[3]);
            unpack2(v2, f[4], f[5]); unpack2(v3, f[6], f[7]);
            float part = 0.f;
#pragma unroll
            for (int j = 0; j < 8; j++) {
                float vv = f[j];
                part = fmaf(att_r[j], fmaxf(vv, 0.2f * vv), part);
            }
#pragma unroll
            for (int off = 1; off < LPH; off <<= 1)
                part += __shfl_xor_sync(FULLMASK, part, off);

            if (part > m) {
                float sc = __expf(m - part);
                s *= sc;
                ull sc2 = dup2(sc);
#pragma unroll
                for (int j = 0; j < 4; j++) acc2[j] = mul2(acc2[j], sc2);
                m = part;
            }
            float pe = __expf(part - m);
            s += pe;
            ull pe2 = dup2(pe);
            fma2(acc2[0], pe2, xl2[0]);
            fma2(acc2[1], pe2, xl2[1]);
            fma2(acc2[2], pe2, xl2[2]);
            fma2(acc2[3], pe2, xl2[3]);
        }
    }

    float inv = (e1 > e0) ? (1.f / s) : 0.f;
    float r[8];
    unpack2(acc2[0], r[0], r[1]); unpack2(acc2[1], r[2], r[3]);
    unpack2(acc2[2], r[4], r[5]); unpack2(acc2[3], r[6], r[7]);

    if (CONCAT) {
        float4 b0 = *(const float4*)(bias + cbase);
        float4 b1 = *(const float4*)(bias + cbase + 4);
        float4 o0, o1;
        o0.x = fmaf(r[0], inv, b0.x); o0.y = fmaf(r[1], inv, b0.y);
        o0.z = fmaf(r[2], inv, b0.z); o0.w = fmaf(r[3], inv, b0.w);
        o1.x = fmaf(r[4], inv, b1.x); o1.y = fmaf(r[5], inv, b1.y);
        o1.z = fmaf(r[6], inv, b1.z); o1.w = fmaf(r[7], inv, b1.w);
        float* q = Hout + (long)n * HC + cbase;
        *(float4*)q = o0;
        *(float4*)(q + 4) = o1;
    } else {
        // mean over 4 heads: shfl 16 pairs the warp's 2 heads; the node's two
        // warps (same block) combine through shared memory.
#pragma unroll
        for (int j = 0; j < 8; j++) {
            r[j] *= inv;
            r[j] += __shfl_xor_sync(FULLMASK, r[j], 16);
        }
        int c = (lane & 15) * 8;
        if (half == 0 && lane < 16) {
#pragma unroll
            for (int j = 0; j < 8; j++) s_red[c + j] = r[j];
        }
        __syncthreads();
        if (half == 1 && lane < 16) {
            float* q = Hout + (long)n * C + c;
#pragma unroll
            for (int j = 0; j < 8; j++)
                q[j] = bias[c + j] + 0.25f * (r[j] + s_red[c + j]);
        }
    }
}

// ---------------- pooling ----------------------------------------------------
__global__ void k_pool_init(float* out, int* gcnt) {
    int i = blockIdx.x * blockDim.x + threadIdx.x;
    if (i < NG * 256) out[i] = ((i & 255) < 128) ? -FLT_MAX : 0.f;
    if (i < NG) gcnt[i] = 0;
}

__global__ void k_pool_acc(const float* __restrict__ H, const int* __restrict__ batch,
                           float* out, int* gcnt) {
    int i = blockIdx.x * blockDim.x + threadIdx.x;
    if (i >= NN * 128) return;
    int nd = i >> 7, c = i & 127;
    int g = batch[nd];
    float v = H[i];
    float* mx = out + g * 256 + c;
    if (v >= 0.f) atomicMax((int*)mx, __float_as_int(v));
    else atomicMin((unsigned int*)mx, __float_as_uint(v));
    atomicAdd(out + g * 256 + 128 + c, v);
    if (c == 0) atomicAdd(&gcnt[g], 1);
}

__global__ void k_pool_fin(float* out, const int* __restrict__ gcnt) {
    int i = blockIdx.x * blockDim.x + threadIdx.x;
    if (i < NG * 128) {
        int g = i >> 7, c = i & 127;
        float cnt = (float)(gcnt[g] > 0 ? gcnt[g] : 1);
        out[g * 256 + 128 + c] /= cnt;
    }
}

// ---------------- launch -----------------------------------------------------
extern "C" void kernel_launch(void* const* d_in, const int* in_sizes, int n_in,
                              void* d_out, int out_size)
{
    const float* x     = (const float*)d_in[0];
    const float* ea    = (const float*)d_in[1];
    const int*   ei    = (const int*)d_in[2];
    const int*   batch = (const int*)d_in[3];
    const float* Wl[3] = {(const float*)d_in[4],  (const float*)d_in[11], (const float*)d_in[18]};
    const float* bl[3] = {(const float*)d_in[5],  (const float*)d_in[12], (const float*)d_in[19]};
    const float* Wr[3] = {(const float*)d_in[6],  (const float*)d_in[13], (const float*)d_in[20]};
    const float* br[3] = {(const float*)d_in[7],  (const float*)d_in[14], (const float*)d_in[21]};
    const float* We[3] = {(const float*)d_in[8],  (const float*)d_in[15], (const float*)d_in[22]};
    const float* At[3] = {(const float*)d_in[9],  (const float*)d_in[16], (const float*)d_in[23]};
    const float* Bi[3] = {(const float*)d_in[10], (const float*)d_in[17], (const float*)d_in[24]};
    float* out = (float*)d_out;

    float *XL, *XR, *HA, *HB, *eacsr;
    int *cnt, *rowptr, *cursor, *csrc, *ceid, *gcnt;
    cudaGetSymbolAddress((void**)&XL, g_XL);
    cudaGetSymbolAddress((void**)&XR, g_XR);
    cudaGetSymbolAddress((void**)&HA, g_HA);
    cudaGetSymbolAddress((void**)&HB, g_HB);
    cudaGetSymbolAddress((void**)&cnt, g_cnt);
    cudaGetSymbolAddress((void**)&rowptr, g_rowptr);
    cudaGetSymbolAddress((void**)&cursor, g_cursor);
    cudaGetSymbolAddress((void**)&csrc, g_csrc);
    cudaGetSymbolAddress((void**)&ceid, g_ceid);
    cudaGetSymbolAddress((void**)&eacsr, g_eacsr);
    cudaGetSymbolAddress((void**)&gcnt, g_gcnt);

    const int MT = (NN + 127) / 128;  // 157

    // ---- CSR histogram + scan (launches 1-3) ----
    k_zero_cnt<<<(NN + 255) / 256, 256>>>(cnt, NN);
    k_hist<<<(NE + 255) / 256, 256>>>(ei, cnt, NE);
    k_scan<<<1, 1024>>>(cnt, rowptr, cursor, NN);

    // ---- launch 4 = ncu capture slot: first GEMM ----
    k_gemm_bias<<<dim3(4, MT), 256>>>(x, Wl[0], bl[0], XL, NN, 256, 128);
    k_gemm_bias<<<dim3(4, MT), 256>>>(x, Wr[0], br[0], XR, NN, 256, 128);

    // ---- finish CSR ----
    k_scatter<<<(NE + 255) / 256, 256>>>(ei, cursor, csrc, ceid, NE);
    k_gather_ea<<<(NE + 255) / 256, 256>>>(ea, ceid, eacsr, NE);

    // ---- layer 0 attention: one 32-thread block per node ----
    k_gat<256, 64, true><<<NN, 32>>>(XL, XR, eacsr, At[0], Bi[0], We[0],
                                     rowptr, csrc, HA, NN);

    // ---- layer 1 ----
    k_gemm_bias<<<dim3(4, MT), 256>>>(HA, Wl[1], bl[1], XL, NN, 256, 256);
    k_gemm_bias<<<dim3(4, MT), 256>>>(HA, Wr[1], br[1], XR, NN, 256, 256);
    k_gat<256, 64, true><<<NN, 32>>>(XL, XR, eacsr, At[1], Bi[1], We[1],
                                     rowptr, csrc, HB, NN);

    // ---- layer 2 (mean over heads): one 64-thread block per node ----
    k_gemm_bias<<<dim3(8, MT), 256>>>(HB, Wl[2], bl[2], XL, NN, 512, 256);
    k_gemm_bias<<<dim3(8, MT), 256>>>(HB, Wr[2], br[2], XR, NN, 512, 256);
    k_gat<512, 128, false><<<NN, 64>>>(XL, XR, eacsr, At[2], Bi[2], We[2],
                                       rowptr, csrc, HA, NN);

    // ---- pooling ----
    k_pool_init<<<64, 256>>>(out, gcnt);
    k_pool_acc<<<(NN * 128 + 255) / 256, 256>>>(HA, batch, out, gcnt);
    k_pool_fin<<<32, 256>>>(out, gcnt);
}